// round 16
// baseline (speedup 1.0000x reference)
#include <cuda_runtime.h>
#include <cuda_bf16.h>
#include <math.h>
#include <stdint.h>

#define B  64
#define TF 64
#define TE 32
#define H  100
#define E  40
#define SP 256
#define EV 20000
#define M2 (B*TE)
#define NPAD 20096

__device__ float g_h[B*H];
__device__ float g_enc[B*TF*H];
__device__ float g_encA[B*TF*200];
__device__ float g_encS[B*TF*SP];
__device__ float g_sp2m[SP+1];
__device__ float g_dec[B*TE*H];
__device__ float g_rows[M2];
__device__ __nv_bfloat16 g_Ah[M2*128];
__device__ __nv_bfloat16 g_Al[M2*128];
__device__ __nv_bfloat16 g_WhT[NPAD*128];
__device__ __nv_bfloat16 g_WlT[NPAD*128];
// packed-k4 decoder weights
__device__ float4 pTa [25*200];
__device__ float4 pTa2[25*200];
__device__ float4 pTq [25*200];
__device__ float4 pTw [25*300];
__device__ float4 pTu [25*300];
__device__ float4 pTs1[25*256];
__device__ float4 pTs2[25*256];
__device__ float4 pTs3[25*256];

__device__ __forceinline__ float sigmoidf_(float x){ return 1.0f/(1.0f+__expf(-x)); }
__device__ __forceinline__ float tanh_poly(float x){
    float t2=x*x;
    float p=fmaf(t2,-0.05396825397f,0.13333333333f);
    p=fmaf(t2,p,-0.33333333333f);
    p=fmaf(t2,p,1.0f);
    return x*p;
}
__device__ __forceinline__ uint32_t s2u(const void* p){ uint32_t a; asm("{ .reg .u64 t; cvta.to.shared.u64 t, %1; cvt.u32.u64 %0, t; }" : "=r"(a) : "l"(p)); return a; }
__device__ __forceinline__ float4 mixf4(float g, float4 v, float4 r){
    v.x=fmaf(g,v.x-r.x,r.x); v.y=fmaf(g,v.y-r.y,r.y);
    v.z=fmaf(g,v.z-r.z,r.z); v.w=fmaf(g,v.w-r.w,r.w); return v;
}
__device__ __forceinline__ float dotp(const float4* __restrict__ W, int Nout, int o, const float4* v4){
    float a0=0.f, a1=0.f;
    #pragma unroll
    for(int k=0;k<25;k++){
        float4 w=W[k*Nout+o]; float4 s=v4[k];
        a0 += w.x*s.x + w.y*s.y;
        a1 += w.z*s.z + w.w*s.w;
    }
    return a0+a1;
}
__device__ __forceinline__ void st_peer(uint32_t laddr, uint32_t peer, float v){
    uint32_t pa;
    asm volatile("mapa.shared::cluster.u32 %0, %1, %2;" : "=r"(pa) : "r"(laddr), "r"(peer));
    asm volatile("st.shared::cluster.f32 [%0], %1;" :: "r"(pa), "f"(v) : "memory");
}
__device__ __forceinline__ void ldm4(uint32_t* r, uint32_t addr){
    asm volatile("ldmatrix.sync.aligned.m8n8.x4.shared.b16 {%0,%1,%2,%3}, [%4];"
      : "=r"(r[0]),"=r"(r[1]),"=r"(r[2]),"=r"(r[3]) : "r"(addr));
}
__device__ __forceinline__ void mma_bf16(float* c, const uint32_t* a, const uint32_t* b){
    asm volatile("mma.sync.aligned.m16n8k16.row.col.f32.bf16.bf16.f32 "
        "{%0,%1,%2,%3}, {%4,%5,%6,%7}, {%8,%9}, {%0,%1,%2,%3};"
        : "+f"(c[0]),"+f"(c[1]),"+f"(c[2]),"+f"(c[3])
        : "r"(a[0]),"r"(a[1]),"r"(a[2]),"r"(a[3]), "r"(b[0]),"r"(b[1]));
}

// ---------------- encoder ----------------
__global__ void k_encoder(const int* __restrict__ enc_in, const float* __restrict__ femb,
                          const float* __restrict__ W, const float* __restrict__ U,
                          const float* __restrict__ bias)
{
    extern __shared__ float sm[];
    float* sW  = sm;
    float* sU  = sW + E*300;
    float* sB  = sU + H*300;
    float* sH  = sB + 600;
    float* sX  = sH + H;
    float* sXs = sX + E;
    float* sHs = sXs + 300;
    int b = blockIdx.x, tid = threadIdx.x, nt = blockDim.x;

    for(int i=tid;i<E*300;i+=nt) sW[i]=W[i];
    for(int i=tid;i<H*300;i+=nt) sU[i]=U[i];
    for(int i=tid;i<600;  i+=nt) sB[i]=bias[i];
    if(tid<H) sH[tid]=0.f;
    __syncthreads();

    for(int t=0;t<TF;t++){
        int tok = enc_in[b*TF+t];
        if(tid<E) sX[tid]=femb[tok*E+tid];
        __syncthreads();
        if(tid<300){
            float a=sB[tid];
            #pragma unroll 8
            for(int k=0;k<E;k++) a += sX[k]*sW[k*300+tid];
            float c=sB[300+tid];
            #pragma unroll 10
            for(int k=0;k<H;k++) c += sH[k]*sU[k*300+tid];
            sXs[tid]=a; sHs[tid]=c;
        }
        __syncthreads();
        if(tid<H){
            float z    = sigmoidf_(sXs[tid]      + sHs[tid]);
            float r    = sigmoidf_(sXs[H+tid]    + sHs[H+tid]);
            float cand = tanhf   (sXs[2*H+tid]  + r*sHs[2*H+tid]);
            float hn   = z*sH[tid] + (1.f-z)*cand;
            sH[tid]=hn;
            g_enc[(b*TF+t)*H+tid]=hn;
        }
        __syncthreads();
    }
    if(tid<H) g_h[b*H+tid]=sH[tid];
}

// ---------------- precompute encA / encS ----------------
__global__ void k_pre(const float* __restrict__ attW1, const float* __restrict__ sp1W)
{
    __shared__ float sE[8*H];
    int r0 = blockIdx.x*8;
    int tid=threadIdx.x;
    for(int i=tid;i<8*H;i+=256) sE[i]=g_enc[r0*H+i];
    __syncthreads();
    for(int idx=tid; idx<8*456; idx+=256){
        int row = idx/456, d = idx-row*456;
        const float* e = sE + row*H;
        float acc=0.f;
        if(d<200){
            #pragma unroll 10
            for(int k=0;k<H;k++) acc += e[k]*attW1[(H+k)*200+d];
            g_encA[(r0+row)*200+d]=acc;
        } else {
            int dd=d-200;
            #pragma unroll 10
            for(int k=0;k<H;k++) acc += e[k]*sp1W[(2*H+k)*SP+dd];
            g_encS[(r0+row)*SP+dd]=acc;
        }
    }
}

// ---------------- pack decoder weights + sp2 row-means ----------------
__global__ void k_wp(const float* __restrict__ attW1, const float* __restrict__ attW2,
                     const float* __restrict__ decW,  const float* __restrict__ decU,
                     const float* __restrict__ sp1W,  const float* __restrict__ sp2W,
                     const float* __restrict__ sp2b)
{
    int i=blockIdx.x*256+threadIdx.x;
    if(i<SP){
        float s=0.f;
        for(int j=0;j<SP;j++) s+=sp2W[i*SP+j];
        g_sp2m[i]=s*(1.f/SP);
    } else if(i==SP){
        float t=0.f;
        for(int j=0;j<SP;j++) t+=sp2b[j];
        g_sp2m[SP]=t*(1.f/SP);
    }
    if(i<25*200){
        int k4=i/200, o=i-k4*200, k=4*k4;
        pTa [i]=make_float4(attW1[k*200+o],attW1[(k+1)*200+o],attW1[(k+2)*200+o],attW1[(k+3)*200+o]);
        pTa2[i]=make_float4(attW1[(100+k)*200+o],attW1[(101+k)*200+o],attW1[(102+k)*200+o],attW1[(103+k)*200+o]);
        pTq [i]=make_float4(attW2[k*200+o],attW2[(k+1)*200+o],attW2[(k+2)*200+o],attW2[(k+3)*200+o]);
    }
    if(i<25*300){
        int k4=i/300, o=i-k4*300, k=4*k4;
        pTw[i]=make_float4(decW[k*300+o],decW[(k+1)*300+o],decW[(k+2)*300+o],decW[(k+3)*300+o]);
        pTu[i]=make_float4(decU[k*300+o],decU[(k+1)*300+o],decU[(k+2)*300+o],decU[(k+3)*300+o]);
    }
    if(i<25*256){
        int k4=i>>8, o=i&255, k=4*k4;
        pTs1[i]=make_float4(sp1W[k*SP+o],sp1W[(k+1)*SP+o],sp1W[(k+2)*SP+o],sp1W[(k+3)*SP+o]);
        pTs2[i]=make_float4(sp1W[(100+k)*SP+o],sp1W[(101+k)*SP+o],sp1W[(102+k)*SP+o],sp1W[(103+k)*SP+o]);
        pTs3[i]=make_float4(sp1W[(200+k)*SP+o],sp1W[(201+k)*SP+o],sp1W[(202+k)*SP+o],sp1W[(203+k)*SP+o]);
    }
}

// ---------------- W transpose + bf16 hi/lo split ----------------
__global__ void k_wt(const float* __restrict__ W)
{
    __shared__ float tile[100*129];
    int n0=blockIdx.x*128, tid=threadIdx.x;
    for(int i=tid;i<100*128;i+=256){
        int k=i>>7, nl=i&127;
        int n=n0+nl;
        tile[k*129+nl]=(n<EV)?W[k*EV+n]:0.f;
    }
    __syncthreads();
    for(int i=tid;i<128*128;i+=256){
        int nl=i>>7, k=i&127;
        float v=(k<100)?tile[k*129+nl]:0.f;
        __nv_bfloat16 h=__float2bfloat16(v);
        float r=v-__bfloat162float(h);
        int o=(n0+nl)*128+k;
        g_WhT[o]=h; g_WlT[o]=__float2bfloat16(r);
    }
}

// ---------------- decoder: cluster-of-2 split-t, duplicated dot phases (R12 exact) ----------------
#define TLOC 32
__global__ void __launch_bounds__(1024,1) __cluster_dims__(2,1,1)
k_decoder(const float* __restrict__ decb, const float* __restrict__ sp1b)
{
    extern __shared__ float sm[];
    float* sEnc   = sm;
    float* sEncA  = sEnc  + TLOC*H;
    float* sEncS  = sEncA + TLOC*200;
    float* sH     = sEncS + TLOC*SP;
    float* sHn    = sH     + H;
    float* sRead  = sHn    + H;
    float* sHbA   = sRead  + H;
    float* sQ     = sHbA   + 200;
    float* sXs    = sQ     + 200;
    float* sHs    = sXs    + 300;
    float* sHrS   = sHs    + 300;
    float* sHrSr  = sHrS   + SP;
    float* sReadA = sHrSr  + SP;
    float* sReadS = sReadA + 200;
    float* sAccP  = sReadS + SP;
    float* sAccR  = sAccP  + 104;
    float* sAccT  = sAccR  + 208;
    float* sG     = sAccT  + 104;
    float* sSp1b  = sG     + 32;
    float* sSp2m  = sSp1b  + SP;
    float* sDecb  = sSp2m  + 260;

    int tid=threadIdx.x;
    int lane = tid&31, wid = tid>>5;
    uint32_t rank; asm("mov.u32 %0, %%cluster_ctarank;" : "=r"(rank));
    uint32_t peer = rank^1u;
    int b = blockIdx.x>>1;

    for(int i=tid;i<TLOC*H;  i+=1024) sEnc[i] =g_enc [b*TF*H   + rank*TLOC*H   + i];
    for(int i=tid;i<TLOC*200;i+=1024) sEncA[i]=g_encA[b*TF*200 + rank*TLOC*200 + i];
    for(int i=tid;i<TLOC*SP; i+=1024) sEncS[i]=g_encS[b*TF*SP  + rank*TLOC*SP  + i];
    for(int i=tid;i<600;     i+=1024) sDecb[i]=decb[i];
    if(tid<SP)   sSp1b[tid]=sp1b[tid];
    if(tid<SP+1) sSp2m[tid]=g_sp2m[tid];
    if(tid<H)    sH[tid]=g_h[b*H+tid];
    __syncthreads();

    {
        const float4* H4=(const float4*)sH;
        if(tid<200)      sHbA[tid]=dotp(pTa,200,tid,H4);
        else if(tid<400){ int o=tid-200; sQ[o]=dotp(pTq,200,o,H4); }
        else if(tid<700){ int u=tid-400; sHs[u]=sDecb[300+u]+dotp(pTu,300,u,H4); }
        else if(tid<801){ sAccP[tid-700]=0.f; }
    }
    __syncthreads();

    for(int s=0;s<TE;s++){
        {
            const float4* A4=(const float4*)(sEncA+wid*200);
            const float4* H4=(const float4*)sHbA;
            const float4* Q4=(const float4*)sQ;
            float p=0.f;
            { int k=lane; float4 a=A4[k],h=H4[k],q=Q4[k];
              p += tanh_poly(h.x+a.x)*q.x + tanh_poly(h.y+a.y)*q.y
                 + tanh_poly(h.z+a.z)*q.z + tanh_poly(h.w+a.w)*q.w; }
            if(lane<18){ int k=lane+32; float4 a=A4[k],h=H4[k],q=Q4[k];
              p += tanh_poly(h.x+a.x)*q.x + tanh_poly(h.y+a.y)*q.y
                 + tanh_poly(h.z+a.z)*q.z + tanh_poly(h.w+a.w)*q.w; }
            #pragma unroll
            for(int o=16;o;o>>=1) p+=__shfl_xor_sync(0xffffffffu,p,o);
            float e=__expf(p);
            if(lane==0) atomicAdd(&sAccP[100], e);
            const float* ep=sEnc+wid*H;
            #pragma unroll
            for(int i=lane;i<H;i+=32) atomicAdd(&sAccP[i], e*ep[i]);
        }
        __syncthreads();
        {
            int buf=(s&1)*104;
            if(tid<101) st_peer(s2u(&sAccR[buf+tid]), peer, sAccP[tid]);
            asm volatile("barrier.cluster.arrive.aligned;" ::: "memory");
            asm volatile("barrier.cluster.wait.aligned;"   ::: "memory");
            if(tid<101) sAccT[tid]=sAccP[tid]+sAccR[buf+tid];
        }
        __syncthreads();
        {
            float inv=1.f/sAccT[100];
            const float4* R4=(const float4*)sAccT;
            if(tid<300)      sXs[tid]=sDecb[tid]+inv*dotp(pTw,300,tid,R4);
            else if(tid<500){ int d=tid-300; sReadA[d]=inv*dotp(pTa2,200,d,R4); }
            else if(tid<756){ int kk=tid-500; sReadS[kk]=inv*dotp(pTs3,256,kk,R4); }
            else if(tid<1012){ int kk=tid-756; sHrSr[kk]=inv*dotp(pTs2,256,kk,R4); }
        }
        __syncthreads();
        if(tid<H){
            float z    = sigmoidf_(sXs[tid]     + sHs[tid]);
            float r    = sigmoidf_(sXs[H+tid]   + sHs[H+tid]);
            float cand = tanhf   (sXs[2*H+tid] + r*sHs[2*H+tid]);
            float hn   = z*sH[tid] + (1.f-z)*cand;
            sHn[tid]=hn;
            if(rank==0) g_dec[(b*TE+s)*H+tid]=hn;
        } else if(tid>=128 && tid<153){
            int j=tid-128;
            float inv=1.f/sAccT[100];
            float4 a=((const float4*)sAccT)[j];
            ((float4*)sRead)[j]=make_float4(a.x*inv,a.y*inv,a.z*inv,a.w*inv);
        }
        __syncthreads();
        if(s==TE-1) break;
        {
            const float4* N4=(const float4*)sHn;
            if(tid<256)      sHrS[tid]=sSp1b[tid]+sHrSr[tid]+dotp(pTs1,256,tid,N4);
            else if(tid<456){ int o=tid-256; sHbA[o]=dotp(pTa,200,o,N4); }
            else if(tid<656){ int o=tid-456; sQ[o]=dotp(pTq,200,o,N4); }
            else if(tid<956){ int u=tid-656; sHs[u]=sDecb[300+u]+dotp(pTu,300,u,N4); }
            else { for(int z=tid-956; z<101; z+=68) sAccP[z]=0.f; }
        }
        __syncthreads();
        {
            const float4* S4=(const float4*)(sEncS+wid*SP);
            const float4* HS4=(const float4*)sHrS;
            const float4* M4=(const float4*)sSp2m;
            float p=0.f;
            #pragma unroll
            for(int j=0;j<2;j++){
                int k=lane+32*j;
                float4 a=S4[k], h=HS4[k], mm=M4[k];
                p += fmaxf(h.x+a.x,0.f)*mm.x + fmaxf(h.y+a.y,0.f)*mm.y
                   + fmaxf(h.z+a.z,0.f)*mm.z + fmaxf(h.w+a.w,0.f)*mm.w;
            }
            #pragma unroll
            for(int o=16;o;o>>=1) p+=__shfl_down_sync(0xffffffffu,p,o);
            if(lane==0) sG[wid]=sigmoidf_(p+sSp2m[SP]);
        }
        __syncthreads();
        {
            float g0=sG[wid];
            const float4* R4=(const float4*)sRead;
            float4* E4=(float4*)sEnc;
            if(lane<25) E4[wid*25+lane]=mixf4(g0,E4[wid*25+lane],R4[lane]);
            const float4* RA4=(const float4*)sReadA;
            float4* A4=(float4*)sEncA;
            { int k=lane; A4[wid*50+k]=mixf4(g0,A4[wid*50+k],RA4[k]); }
            if(lane<18){ int k=lane+32; A4[wid*50+k]=mixf4(g0,A4[wid*50+k],RA4[k]); }
            const float4* RS4=(const float4*)sReadS;
            float4* S4=(float4*)sEncS;
            #pragma unroll
            for(int j=0;j<2;j++){
                int k=lane+32*j;
                S4[wid*64+k]=mixf4(g0,S4[wid*64+k],RS4[k]);
            }
        }
        if(tid<H) sH[tid]=sHn[tid];
        __syncthreads();
    }
}

// ---------------- ff1 + relu -> bf16 hi/lo (also zeroes g_rows) ----------------
__global__ void k_ff1(const float* __restrict__ W, const float* __restrict__ bias)
{
    __shared__ float sRow[H];
    int m=blockIdx.x, tid=threadIdx.x;
    if(tid<H) sRow[tid]=g_dec[m*H+tid];
    __syncthreads();
    float v=0.f;
    if(tid<H){
        float acc=bias[tid];
        #pragma unroll 10
        for(int k=0;k<H;k++) acc+=sRow[k]*W[k*H+tid];
        v=fmaxf(acc,0.f);
    }
    __nv_bfloat16 h=__float2bfloat16(v);
    float r=v-__bfloat162float(h);
    g_Ah[m*128+tid]=h; g_Al[m*128+tid]=__float2bfloat16(r);
    if(tid==0) g_rows[m]=0.f;
}

// ---------------- HMMA GEMM 128m x 128n, 256 threads (R12 exact) ----------------
#define STR 136
#define TBY (STR*2)
#define SOF_AH 1024
#define SOF_AL (SOF_AH + 128*TBY)
#define SOF_WH (SOF_AL + 128*TBY)
#define SOF_WL (SOF_WH + 128*TBY)
#define GSMEM  (SOF_WL + 128*TBY)

__global__ void __launch_bounds__(256,1)
k_gemm(const float* __restrict__ ff2b, float* __restrict__ out)
{
    extern __shared__ char smc[];
    float* sBias=(float*)smc;
    uint32_t sb = s2u(smc);
    int tid=threadIdx.x, wid=tid>>5, lane=tid&31;
    int n0=blockIdx.x*128, m0=blockIdx.y*128;

    if(tid<128) sBias[tid]=(n0+tid<EV)?ff2b[n0+tid]:0.f;

    {
        const uint4* Ah4=(const uint4*)g_Ah;
        const uint4* Al4=(const uint4*)g_Al;
        const uint4* Wh4=(const uint4*)g_WhT;
        const uint4* Wl4=(const uint4*)g_WlT;
        for(int c=tid;c<2048;c+=256){
            int rr=c>>4, kc=c&15;
            uint32_t d = rr*TBY + kc*16;
            *(uint4*)(smc+SOF_AH+d)=Ah4[(m0+rr)*16+kc];
            *(uint4*)(smc+SOF_AL+d)=Al4[(m0+rr)*16+kc];
            *(uint4*)(smc+SOF_WH+d)=Wh4[(n0+rr)*16+kc];
            *(uint4*)(smc+SOF_WL+d)=Wl4[(n0+rr)*16+kc];
        }
    }
    __syncthreads();

    int wm=(wid>>1)*32, wn=(wid&1)*64;
    int rA=(lane&7)+((lane>>3)&1)*8, cA=((lane>>4)&1)*8;
    int rB=(lane&7)+((lane>>4)&1)*8, cB=((lane>>3)&1)*8;

    float c[2][8][4];
    #pragma unroll
    for(int i=0;i<2;i++)
        #pragma unroll
        for(int j=0;j<8;j++)
            #pragma unroll
            for(int q=0;q<4;q++) c[i][j][q]=0.f;

    #pragma unroll
    for(int p=0;p<3;p++){
        uint32_t aP = sb + (p==1?SOF_AL:SOF_AH);
        uint32_t bP = sb + (p==2?SOF_WL:SOF_WH);
        uint32_t aBase = aP + (uint32_t)((wm+rA)*STR+cA)*2u;
        uint32_t bBase = bP + (uint32_t)((wn+rB)*STR+cB)*2u;
        #pragma unroll
        for(int k=0;k<8;k++){
            uint32_t a0[4],a1[4];
            ldm4(a0, aBase + k*32u);
            ldm4(a1, aBase + 16u*TBY + k*32u);
            #pragma unroll
            for(int jj=0;jj<4;jj++){
                uint32_t bb[4];
                ldm4(bb, bBase + jj*16u*TBY + k*32u);
                mma_bf16(c[0][jj*2],   a0, bb);
                mma_bf16(c[0][jj*2+1], a0, bb+2);
                mma_bf16(c[1][jj*2],   a1, bb);
                mma_bf16(c[1][jj*2+1], a1, bb+2);
            }
        }
    }

    #pragma unroll
    for(int mf=0;mf<2;mf++){
        int r0=m0+wm+mf*16+(lane>>2);
        float rs0=0.f, rs1=0.f;
        #pragma unroll
        for(int j=0;j<8;j++){
            int col=n0+wn+j*8+(lane&3)*2;
            int bcol=wn+j*8+(lane&3)*2;
            if(col<EV){
                float2 v0,v1;
                v0.x=__expf(c[mf][j][0]+sBias[bcol]);
                v0.y=__expf(c[mf][j][1]+sBias[bcol+1]);
                v1.x=__expf(c[mf][j][2]+sBias[bcol]);
                v1.y=__expf(c[mf][j][3]+sBias[bcol+1]);
                rs0+=v0.x+v0.y; rs1+=v1.x+v1.y;
                *(float2*)&out[(size_t)r0*EV+col]=v0;
                *(float2*)&out[(size_t)(r0+8)*EV+col]=v1;
            }
        }
        rs0+=__shfl_down_sync(0xffffffffu,rs0,1,4);
        rs0+=__shfl_down_sync(0xffffffffu,rs0,2,4);
        rs1+=__shfl_down_sync(0xffffffffu,rs1,1,4);
        rs1+=__shfl_down_sync(0xffffffffu,rs1,2,4);
        if((lane&3)==0){
            atomicAdd(&g_rows[r0], rs0);
            atomicAdd(&g_rows[r0+8], rs1);
        }
    }
}

// ---------------- normalize ----------------
__global__ void k_norm(float* __restrict__ out)
{
    int row=blockIdx.x, tid=threadIdx.x;
    float inv=1.f/g_rows[row];
    float4* p4=(float4*)(out+(size_t)row*EV);
    for(int j=tid;j<EV/4;j+=256){
        float4 v=p4[j];
        v.x*=inv; v.y*=inv; v.z*=inv; v.w*=inv;
        p4[j]=v;
    }
}

// ---------------- launch: MEASUREMENT ROUND — gemm pass duplicated ----------------
// Second ff1 re-zeroes g_rows; second gemm deterministically rewrites out and
// re-accumulates rows. Output identical to single pass; dur delta vs the 932us
// baseline == dur(gemm) + dur(ff1), giving ground-truth gemm attribution.
extern "C" void kernel_launch(void* const* d_in, const int* in_sizes, int n_in,
                              void* d_out, int out_size)
{
    (void)in_sizes; (void)n_in; (void)out_size;
    const int*   enc_in=(const int*)  d_in[0];
    const float* femb  =(const float*)d_in[2];
    const float* encW  =(const float*)d_in[4];
    const float* encU  =(const float*)d_in[5];
    const float* encb  =(const float*)d_in[6];
    const float* decW  =(const float*)d_in[7];
    const float* decU  =(const float*)d_in[8];
    const float* decb  =(const float*)d_in[9];
    const float* attW1 =(const float*)d_in[10];
    const float* attW2 =(const float*)d_in[11];
    const float* sp1W  =(const float*)d_in[12];
    const float* sp1b  =(const float*)d_in[13];
    const float* sp2W  =(const float*)d_in[14];
    const float* sp2b  =(const float*)d_in[15];
    const float* ff1W  =(const float*)d_in[16];
    const float* ff1b  =(const float*)d_in[17];
    const float* ff2W  =(const float*)d_in[18];
    const float* ff2b  =(const float*)d_in[19];
    float* out=(float*)d_out;

    static const int ENC_SMEM = (E*300 + H*300 + 600 + H + E + 300 + 300)*4;
    static const int DEC_SMEM = (TLOC*H + TLOC*200 + TLOC*SP + 4228)*4;

    cudaFuncSetAttribute(k_encoder, cudaFuncAttributeMaxDynamicSharedMemorySize, ENC_SMEM);
    cudaFuncSetAttribute(k_decoder, cudaFuncAttributeMaxDynamicSharedMemorySize, DEC_SMEM);
    cudaFuncSetAttribute(k_gemm,    cudaFuncAttributeMaxDynamicSharedMemorySize, GSMEM);

    k_encoder<<<B,320,ENC_SMEM>>>(enc_in,femb,encW,encU,encb);
    k_pre    <<<(B*TF)/8,256>>>(attW1,sp1W);
    k_wp     <<<30,256>>>(attW1,attW2,decW,decU,sp1W,sp2W,sp2b);
    k_decoder<<<2*B,1024,DEC_SMEM>>>(decb,sp1b);
    k_wt     <<<NPAD/128,256>>>(ff2W);
    k_ff1    <<<M2,128>>>(ff1W,ff1b);
    k_gemm   <<<dim3(NPAD/128, M2/128),256,GSMEM>>>(ff2b,out);
    // --- duplicated measurement pass (correctness-preserving) ---
    k_ff1    <<<M2,128>>>(ff1W,ff1b);
    k_gemm   <<<dim3(NPAD/128, M2/128),256,GSMEM>>>(ff2b,out);
    k_norm   <<<M2,256>>>(out);
}

// round 17
// speedup vs baseline: 1.1767x; 1.1767x over previous
#include <cuda_runtime.h>
#include <cuda_bf16.h>
#include <math.h>
#include <stdint.h>

#define B  64
#define TF 64
#define TE 32
#define H  100
#define E  40
#define SP 256
#define EV 20000
#define M2 (B*TE)
#define NPAD 20096

__device__ float g_h[B*H];
__device__ float g_enc[B*TF*H];
__device__ float g_encA[B*TF*200];
__device__ float g_encS[B*TF*SP];
__device__ float g_sp2m[SP+1];
__device__ float g_dec[B*TE*H];
__device__ float g_rows[M2];
__device__ __nv_bfloat16 g_Ah[M2*128];
__device__ __nv_bfloat16 g_Al[M2*128];
__device__ __nv_bfloat16 g_WhT[NPAD*128];
__device__ __nv_bfloat16 g_WlT[NPAD*128];
// packed-k4 decoder weights
__device__ float4 pTa [25*200];
__device__ float4 pTa2[25*200];
__device__ float4 pTq [25*200];
__device__ float4 pTw [25*300];
__device__ float4 pTu [25*300];
__device__ float4 pTs1[25*256];
__device__ float4 pTs2[25*256];
__device__ float4 pTs3[25*256];

__device__ __forceinline__ float sigmoidf_(float x){ return 1.0f/(1.0f+__expf(-x)); }
__device__ __forceinline__ float tanh_poly(float x){
    float t2=x*x;
    float p=fmaf(t2,-0.05396825397f,0.13333333333f);
    p=fmaf(t2,p,-0.33333333333f);
    p=fmaf(t2,p,1.0f);
    return x*p;
}
__device__ __forceinline__ uint32_t s2u(const void* p){ uint32_t a; asm("{ .reg .u64 t; cvta.to.shared.u64 t, %1; cvt.u32.u64 %0, t; }" : "=r"(a) : "l"(p)); return a; }
__device__ __forceinline__ float4 mixf4(float g, float4 v, float4 r){
    v.x=fmaf(g,v.x-r.x,r.x); v.y=fmaf(g,v.y-r.y,r.y);
    v.z=fmaf(g,v.z-r.z,r.z); v.w=fmaf(g,v.w-r.w,r.w); return v;
}
__device__ __forceinline__ float dotp(const float4* __restrict__ W, int Nout, int o, const float4* v4){
    float a0=0.f, a1=0.f;
    #pragma unroll
    for(int k=0;k<25;k++){
        float4 w=W[k*Nout+o]; float4 s=v4[k];
        a0 += w.x*s.x + w.y*s.y;
        a1 += w.z*s.z + w.w*s.w;
    }
    return a0+a1;
}
__device__ __forceinline__ void st_peer(uint32_t laddr, uint32_t peer, float v){
    uint32_t pa;
    asm volatile("mapa.shared::cluster.u32 %0, %1, %2;" : "=r"(pa) : "r"(laddr), "r"(peer));
    asm volatile("st.shared::cluster.f32 [%0], %1;" :: "r"(pa), "f"(v) : "memory");
}
__device__ __forceinline__ void ldm4(uint32_t* r, uint32_t addr){
    asm volatile("ldmatrix.sync.aligned.m8n8.x4.shared.b16 {%0,%1,%2,%3}, [%4];"
      : "=r"(r[0]),"=r"(r[1]),"=r"(r[2]),"=r"(r[3]) : "r"(addr));
}
__device__ __forceinline__ void mma_bf16(float* c, const uint32_t* a, const uint32_t* b){
    asm volatile("mma.sync.aligned.m16n8k16.row.col.f32.bf16.bf16.f32 "
        "{%0,%1,%2,%3}, {%4,%5,%6,%7}, {%8,%9}, {%0,%1,%2,%3};"
        : "+f"(c[0]),"+f"(c[1]),"+f"(c[2]),"+f"(c[3])
        : "r"(a[0]),"r"(a[1]),"r"(a[2]),"r"(a[3]), "r"(b[0]),"r"(b[1]));
}

// ---------------- encoder ----------------
__global__ void k_encoder(const int* __restrict__ enc_in, const float* __restrict__ femb,
                          const float* __restrict__ W, const float* __restrict__ U,
                          const float* __restrict__ bias)
{
    extern __shared__ float sm[];
    float* sW  = sm;
    float* sU  = sW + E*300;
    float* sB  = sU + H*300;
    float* sH  = sB + 600;
    float* sX  = sH + H;
    float* sXs = sX + E;
    float* sHs = sXs + 300;
    int b = blockIdx.x, tid = threadIdx.x, nt = blockDim.x;

    for(int i=tid;i<E*300;i+=nt) sW[i]=W[i];
    for(int i=tid;i<H*300;i+=nt) sU[i]=U[i];
    for(int i=tid;i<600;  i+=nt) sB[i]=bias[i];
    if(tid<H) sH[tid]=0.f;
    __syncthreads();

    for(int t=0;t<TF;t++){
        int tok = enc_in[b*TF+t];
        if(tid<E) sX[tid]=femb[tok*E+tid];
        __syncthreads();
        if(tid<300){
            float a=sB[tid];
            #pragma unroll 8
            for(int k=0;k<E;k++) a += sX[k]*sW[k*300+tid];
            float c=sB[300+tid];
            #pragma unroll 10
            for(int k=0;k<H;k++) c += sH[k]*sU[k*300+tid];
            sXs[tid]=a; sHs[tid]=c;
        }
        __syncthreads();
        if(tid<H){
            float z    = sigmoidf_(sXs[tid]      + sHs[tid]);
            float r    = sigmoidf_(sXs[H+tid]    + sHs[H+tid]);
            float cand = tanhf   (sXs[2*H+tid]  + r*sHs[2*H+tid]);
            float hn   = z*sH[tid] + (1.f-z)*cand;
            sH[tid]=hn;
            g_enc[(b*TF+t)*H+tid]=hn;
        }
        __syncthreads();
    }
    if(tid<H) g_h[b*H+tid]=sH[tid];
}

// ---------------- precompute encA / encS ----------------
__global__ void k_pre(const float* __restrict__ attW1, const float* __restrict__ sp1W)
{
    __shared__ float sE[8*H];
    int r0 = blockIdx.x*8;
    int tid=threadIdx.x;
    for(int i=tid;i<8*H;i+=256) sE[i]=g_enc[r0*H+i];
    __syncthreads();
    for(int idx=tid; idx<8*456; idx+=256){
        int row = idx/456, d = idx-row*456;
        const float* e = sE + row*H;
        float acc=0.f;
        if(d<200){
            #pragma unroll 10
            for(int k=0;k<H;k++) acc += e[k]*attW1[(H+k)*200+d];
            g_encA[(r0+row)*200+d]=acc;
        } else {
            int dd=d-200;
            #pragma unroll 10
            for(int k=0;k<H;k++) acc += e[k]*sp1W[(2*H+k)*SP+dd];
            g_encS[(r0+row)*SP+dd]=acc;
        }
    }
}

// ---------------- pack decoder weights + sp2 row-means ----------------
__global__ void k_wp(const float* __restrict__ attW1, const float* __restrict__ attW2,
                     const float* __restrict__ decW,  const float* __restrict__ decU,
                     const float* __restrict__ sp1W,  const float* __restrict__ sp2W,
                     const float* __restrict__ sp2b)
{
    int i=blockIdx.x*256+threadIdx.x;
    if(i<SP){
        float s=0.f;
        for(int j=0;j<SP;j++) s+=sp2W[i*SP+j];
        g_sp2m[i]=s*(1.f/SP);
    } else if(i==SP){
        float t=0.f;
        for(int j=0;j<SP;j++) t+=sp2b[j];
        g_sp2m[SP]=t*(1.f/SP);
    }
    if(i<25*200){
        int k4=i/200, o=i-k4*200, k=4*k4;
        pTa [i]=make_float4(attW1[k*200+o],attW1[(k+1)*200+o],attW1[(k+2)*200+o],attW1[(k+3)*200+o]);
        pTa2[i]=make_float4(attW1[(100+k)*200+o],attW1[(101+k)*200+o],attW1[(102+k)*200+o],attW1[(103+k)*200+o]);
        pTq [i]=make_float4(attW2[k*200+o],attW2[(k+1)*200+o],attW2[(k+2)*200+o],attW2[(k+3)*200+o]);
    }
    if(i<25*300){
        int k4=i/300, o=i-k4*300, k=4*k4;
        pTw[i]=make_float4(decW[k*300+o],decW[(k+1)*300+o],decW[(k+2)*300+o],decW[(k+3)*300+o]);
        pTu[i]=make_float4(decU[k*300+o],decU[(k+1)*300+o],decU[(k+2)*300+o],decU[(k+3)*300+o]);
    }
    if(i<25*256){
        int k4=i>>8, o=i&255, k=4*k4;
        pTs1[i]=make_float4(sp1W[k*SP+o],sp1W[(k+1)*SP+o],sp1W[(k+2)*SP+o],sp1W[(k+3)*SP+o]);
        pTs2[i]=make_float4(sp1W[(100+k)*SP+o],sp1W[(101+k)*SP+o],sp1W[(102+k)*SP+o],sp1W[(103+k)*SP+o]);
        pTs3[i]=make_float4(sp1W[(200+k)*SP+o],sp1W[(201+k)*SP+o],sp1W[(202+k)*SP+o],sp1W[(203+k)*SP+o]);
    }
}

// ---------------- W transpose + bf16 hi/lo split ----------------
__global__ void k_wt(const float* __restrict__ W)
{
    __shared__ float tile[100*129];
    int n0=blockIdx.x*128, tid=threadIdx.x;
    for(int i=tid;i<100*128;i+=256){
        int k=i>>7, nl=i&127;
        int n=n0+nl;
        tile[k*129+nl]=(n<EV)?W[k*EV+n]:0.f;
    }
    __syncthreads();
    for(int i=tid;i<128*128;i+=256){
        int nl=i>>7, k=i&127;
        float v=(k<100)?tile[k*129+nl]:0.f;
        __nv_bfloat16 h=__float2bfloat16(v);
        float r=v-__bfloat162float(h);
        int o=(n0+nl)*128+k;
        g_WhT[o]=h; g_WlT[o]=__float2bfloat16(r);
    }
}

// ---------------- decoder: cluster-of-2 split-t, duplicated dot phases (R12 exact) ----------------
#define TLOC 32
__global__ void __launch_bounds__(1024,1) __cluster_dims__(2,1,1)
k_decoder(const float* __restrict__ decb, const float* __restrict__ sp1b)
{
    extern __shared__ float sm[];
    float* sEnc   = sm;
    float* sEncA  = sEnc  + TLOC*H;
    float* sEncS  = sEncA + TLOC*200;
    float* sH     = sEncS + TLOC*SP;
    float* sHn    = sH     + H;
    float* sRead  = sHn    + H;
    float* sHbA   = sRead  + H;
    float* sQ     = sHbA   + 200;
    float* sXs    = sQ     + 200;
    float* sHs    = sXs    + 300;
    float* sHrS   = sHs    + 300;
    float* sHrSr  = sHrS   + SP;
    float* sReadA = sHrSr  + SP;
    float* sReadS = sReadA + 200;
    float* sAccP  = sReadS + SP;
    float* sAccR  = sAccP  + 104;
    float* sAccT  = sAccR  + 208;
    float* sG     = sAccT  + 104;
    float* sSp1b  = sG     + 32;
    float* sSp2m  = sSp1b  + SP;
    float* sDecb  = sSp2m  + 260;

    int tid=threadIdx.x;
    int lane = tid&31, wid = tid>>5;
    uint32_t rank; asm("mov.u32 %0, %%cluster_ctarank;" : "=r"(rank));
    uint32_t peer = rank^1u;
    int b = blockIdx.x>>1;

    for(int i=tid;i<TLOC*H;  i+=1024) sEnc[i] =g_enc [b*TF*H   + rank*TLOC*H   + i];
    for(int i=tid;i<TLOC*200;i+=1024) sEncA[i]=g_encA[b*TF*200 + rank*TLOC*200 + i];
    for(int i=tid;i<TLOC*SP; i+=1024) sEncS[i]=g_encS[b*TF*SP  + rank*TLOC*SP  + i];
    for(int i=tid;i<600;     i+=1024) sDecb[i]=decb[i];
    if(tid<SP)   sSp1b[tid]=sp1b[tid];
    if(tid<SP+1) sSp2m[tid]=g_sp2m[tid];
    if(tid<H)    sH[tid]=g_h[b*H+tid];
    __syncthreads();

    {
        const float4* H4=(const float4*)sH;
        if(tid<200)      sHbA[tid]=dotp(pTa,200,tid,H4);
        else if(tid<400){ int o=tid-200; sQ[o]=dotp(pTq,200,o,H4); }
        else if(tid<700){ int u=tid-400; sHs[u]=sDecb[300+u]+dotp(pTu,300,u,H4); }
        else if(tid<801){ sAccP[tid-700]=0.f; }
    }
    __syncthreads();

    for(int s=0;s<TE;s++){
        {
            const float4* A4=(const float4*)(sEncA+wid*200);
            const float4* H4=(const float4*)sHbA;
            const float4* Q4=(const float4*)sQ;
            float p=0.f;
            { int k=lane; float4 a=A4[k],h=H4[k],q=Q4[k];
              p += tanh_poly(h.x+a.x)*q.x + tanh_poly(h.y+a.y)*q.y
                 + tanh_poly(h.z+a.z)*q.z + tanh_poly(h.w+a.w)*q.w; }
            if(lane<18){ int k=lane+32; float4 a=A4[k],h=H4[k],q=Q4[k];
              p += tanh_poly(h.x+a.x)*q.x + tanh_poly(h.y+a.y)*q.y
                 + tanh_poly(h.z+a.z)*q.z + tanh_poly(h.w+a.w)*q.w; }
            #pragma unroll
            for(int o=16;o;o>>=1) p+=__shfl_xor_sync(0xffffffffu,p,o);
            float e=__expf(p);
            if(lane==0) atomicAdd(&sAccP[100], e);
            const float* ep=sEnc+wid*H;
            #pragma unroll
            for(int i=lane;i<H;i+=32) atomicAdd(&sAccP[i], e*ep[i]);
        }
        __syncthreads();
        {
            int buf=(s&1)*104;
            if(tid<101) st_peer(s2u(&sAccR[buf+tid]), peer, sAccP[tid]);
            asm volatile("barrier.cluster.arrive.aligned;" ::: "memory");
            asm volatile("barrier.cluster.wait.aligned;"   ::: "memory");
            if(tid<101) sAccT[tid]=sAccP[tid]+sAccR[buf+tid];
        }
        __syncthreads();
        {
            float inv=1.f/sAccT[100];
            const float4* R4=(const float4*)sAccT;
            if(tid<300)      sXs[tid]=sDecb[tid]+inv*dotp(pTw,300,tid,R4);
            else if(tid<500){ int d=tid-300; sReadA[d]=inv*dotp(pTa2,200,d,R4); }
            else if(tid<756){ int kk=tid-500; sReadS[kk]=inv*dotp(pTs3,256,kk,R4); }
            else if(tid<1012){ int kk=tid-756; sHrSr[kk]=inv*dotp(pTs2,256,kk,R4); }
        }
        __syncthreads();
        if(tid<H){
            float z    = sigmoidf_(sXs[tid]     + sHs[tid]);
            float r    = sigmoidf_(sXs[H+tid]   + sHs[H+tid]);
            float cand = tanhf   (sXs[2*H+tid] + r*sHs[2*H+tid]);
            float hn   = z*sH[tid] + (1.f-z)*cand;
            sHn[tid]=hn;
            if(rank==0) g_dec[(b*TE+s)*H+tid]=hn;
        } else if(tid>=128 && tid<153){
            int j=tid-128;
            float inv=1.f/sAccT[100];
            float4 a=((const float4*)sAccT)[j];
            ((float4*)sRead)[j]=make_float4(a.x*inv,a.y*inv,a.z*inv,a.w*inv);
        }
        __syncthreads();
        if(s==TE-1) break;
        {
            const float4* N4=(const float4*)sHn;
            if(tid<256)      sHrS[tid]=sSp1b[tid]+sHrSr[tid]+dotp(pTs1,256,tid,N4);
            else if(tid<456){ int o=tid-256; sHbA[o]=dotp(pTa,200,o,N4); }
            else if(tid<656){ int o=tid-456; sQ[o]=dotp(pTq,200,o,N4); }
            else if(tid<956){ int u=tid-656; sHs[u]=sDecb[300+u]+dotp(pTu,300,u,N4); }
            else { for(int z=tid-956; z<101; z+=68) sAccP[z]=0.f; }
        }
        __syncthreads();
        {
            const float4* S4=(const float4*)(sEncS+wid*SP);
            const float4* HS4=(const float4*)sHrS;
            const float4* M4=(const float4*)sSp2m;
            float p=0.f;
            #pragma unroll
            for(int j=0;j<2;j++){
                int k=lane+32*j;
                float4 a=S4[k], h=HS4[k], mm=M4[k];
                p += fmaxf(h.x+a.x,0.f)*mm.x + fmaxf(h.y+a.y,0.f)*mm.y
                   + fmaxf(h.z+a.z,0.f)*mm.z + fmaxf(h.w+a.w,0.f)*mm.w;
            }
            #pragma unroll
            for(int o=16;o;o>>=1) p+=__shfl_down_sync(0xffffffffu,p,o);
            if(lane==0) sG[wid]=sigmoidf_(p+sSp2m[SP]);
        }
        __syncthreads();
        {
            float g0=sG[wid];
            const float4* R4=(const float4*)sRead;
            float4* E4=(float4*)sEnc;
            if(lane<25) E4[wid*25+lane]=mixf4(g0,E4[wid*25+lane],R4[lane]);
            const float4* RA4=(const float4*)sReadA;
            float4* A4=(float4*)sEncA;
            { int k=lane; A4[wid*50+k]=mixf4(g0,A4[wid*50+k],RA4[k]); }
            if(lane<18){ int k=lane+32; A4[wid*50+k]=mixf4(g0,A4[wid*50+k],RA4[k]); }
            const float4* RS4=(const float4*)sReadS;
            float4* S4=(float4*)sEncS;
            #pragma unroll
            for(int j=0;j<2;j++){
                int k=lane+32*j;
                S4[wid*64+k]=mixf4(g0,S4[wid*64+k],RS4[k]);
            }
        }
        if(tid<H) sH[tid]=sHn[tid];
        __syncthreads();
    }
}

// ---------------- ff1 + relu -> bf16 hi/lo ----------------
__global__ void k_ff1(const float* __restrict__ W, const float* __restrict__ bias)
{
    __shared__ float sRow[H];
    int m=blockIdx.x, tid=threadIdx.x;
    if(tid<H) sRow[tid]=g_dec[m*H+tid];
    __syncthreads();
    float v=0.f;
    if(tid<H){
        float acc=bias[tid];
        #pragma unroll 10
        for(int k=0;k<H;k++) acc+=sRow[k]*W[k*H+tid];
        v=fmaxf(acc,0.f);
    }
    __nv_bfloat16 h=__float2bfloat16(v);
    float r=v-__bfloat162float(h);
    g_Ah[m*128+tid]=h; g_Al[m*128+tid]=__float2bfloat16(r);
    if(tid==0) g_rows[m]=0.f;
}

// ---------------- HMMA GEMM 64m x 128n, occ 2 (R8 gemm), fused exp/rowsum ----------------
#define STR 136
#define TBY (STR*2)
#define SOF_AH 1024
#define SOF_AL (SOF_AH + 64*TBY)
#define SOF_WH (SOF_AL + 64*TBY)
#define SOF_WL (SOF_WH + 128*TBY)
#define GSMEM  (SOF_WL + 128*TBY)

__global__ void __launch_bounds__(256,2)
k_gemm(const float* __restrict__ ff2b, float* __restrict__ out)
{
    extern __shared__ char smc[];
    float* sBias=(float*)smc;
    uint32_t sb = s2u(smc);
    int tid=threadIdx.x, wid=tid>>5, lane=tid&31;
    int n0=blockIdx.x*128, m0=blockIdx.y*64;

    if(tid<128) sBias[tid]=(n0+tid<EV)?ff2b[n0+tid]:0.f;

    {
        const uint4* Ah4=(const uint4*)g_Ah;
        const uint4* Al4=(const uint4*)g_Al;
        const uint4* Wh4=(const uint4*)g_WhT;
        const uint4* Wl4=(const uint4*)g_WlT;
        for(int c=tid;c<1024;c+=256){
            int rr=c>>4, kc=c&15;
            uint32_t d = rr*TBY + kc*16;
            *(uint4*)(smc+SOF_AH+d)=Ah4[(m0+rr)*16+kc];
            *(uint4*)(smc+SOF_AL+d)=Al4[(m0+rr)*16+kc];
        }
        for(int c=tid;c<2048;c+=256){
            int rr=c>>4, kc=c&15;
            uint32_t d = rr*TBY + kc*16;
            *(uint4*)(smc+SOF_WH+d)=Wh4[(n0+rr)*16+kc];
            *(uint4*)(smc+SOF_WL+d)=Wl4[(n0+rr)*16+kc];
        }
    }
    __syncthreads();

    int wm=(wid&1)*32, wn=(wid>>1)*32;
    int rA=(lane&7)+((lane>>3)&1)*8, cA=((lane>>4)&1)*8;
    int rB=(lane&7)+((lane>>4)&1)*8, cB=((lane>>3)&1)*8;

    float c[2][4][4];
    #pragma unroll
    for(int i=0;i<2;i++)
        #pragma unroll
        for(int j=0;j<4;j++)
            #pragma unroll
            for(int q=0;q<4;q++) c[i][j][q]=0.f;

    #pragma unroll
    for(int p=0;p<3;p++){
        uint32_t aP = sb + (p==1?SOF_AL:SOF_AH);
        uint32_t bP = sb + (p==2?SOF_WL:SOF_WH);
        uint32_t aBase = aP + (uint32_t)((wm+rA)*STR+cA)*2u;
        uint32_t bBase = bP + (uint32_t)((wn+rB)*STR+cB)*2u;
        #pragma unroll
        for(int k=0;k<8;k++){
            uint32_t a0[4],a1[4];
            ldm4(a0, aBase + k*32u);
            ldm4(a1, aBase + 16u*TBY + k*32u);
            #pragma unroll
            for(int jj=0;jj<2;jj++){
                uint32_t bb[4];
                ldm4(bb, bBase + jj*16u*TBY + k*32u);
                mma_bf16(c[0][jj*2],   a0, bb);
                mma_bf16(c[0][jj*2+1], a0, bb+2);
                mma_bf16(c[1][jj*2],   a1, bb);
                mma_bf16(c[1][jj*2+1], a1, bb+2);
            }
        }
    }

    #pragma unroll
    for(int mf=0;mf<2;mf++){
        int r0=m0+wm+mf*16+(lane>>2);
        float rs0=0.f, rs1=0.f;
        #pragma unroll
        for(int j=0;j<4;j++){
            int col=n0+wn+j*8+(lane&3)*2;
            int bcol=wn+j*8+(lane&3)*2;
            if(col<EV){
                float2 v0,v1;
                v0.x=__expf(c[mf][j][0]+sBias[bcol]);
                v0.y=__expf(c[mf][j][1]+sBias[bcol+1]);
                v1.x=__expf(c[mf][j][2]+sBias[bcol]);
                v1.y=__expf(c[mf][j][3]+sBias[bcol+1]);
                rs0+=v0.x+v0.y; rs1+=v1.x+v1.y;
                *(float2*)&out[(size_t)r0*EV+col]=v0;
                *(float2*)&out[(size_t)(r0+8)*EV+col]=v1;
            }
        }
        rs0+=__shfl_down_sync(0xffffffffu,rs0,1,4);
        rs0+=__shfl_down_sync(0xffffffffu,rs0,2,4);
        rs1+=__shfl_down_sync(0xffffffffu,rs1,1,4);
        rs1+=__shfl_down_sync(0xffffffffu,rs1,2,4);
        if((lane&3)==0){
            atomicAdd(&g_rows[r0], rs0);
            atomicAdd(&g_rows[r0+8], rs1);
        }
    }
}

// ---------------- normalize ----------------
__global__ void k_norm(float* __restrict__ out)
{
    int row=blockIdx.x, tid=threadIdx.x;
    float inv=1.f/g_rows[row];
    float4* p4=(float4*)(out+(size_t)row*EV);
    for(int j=tid;j<EV/4;j+=256){
        float4 v=p4[j];
        v.x*=inv; v.y*=inv; v.z*=inv; v.w*=inv;
        p4[j]=v;
    }
}

// ---------------- launch ----------------
extern "C" void kernel_launch(void* const* d_in, const int* in_sizes, int n_in,
                              void* d_out, int out_size)
{
    (void)in_sizes; (void)n_in; (void)out_size;
    const int*   enc_in=(const int*)  d_in[0];
    const float* femb  =(const float*)d_in[2];
    const float* encW  =(const float*)d_in[4];
    const float* encU  =(const float*)d_in[5];
    const float* encb  =(const float*)d_in[6];
    const float* decW  =(const float*)d_in[7];
    const float* decU  =(const float*)d_in[8];
    const float* decb  =(const float*)d_in[9];
    const float* attW1 =(const float*)d_in[10];
    const float* attW2 =(const float*)d_in[11];
    const float* sp1W  =(const float*)d_in[12];
    const float* sp1b  =(const float*)d_in[13];
    const float* sp2W  =(const float*)d_in[14];
    const float* sp2b  =(const float*)d_in[15];
    const float* ff1W  =(const float*)d_in[16];
    const float* ff1b  =(const float*)d_in[17];
    const float* ff2W  =(const float*)d_in[18];
    const float* ff2b  =(const float*)d_in[19];
    float* out=(float*)d_out;

    static const int ENC_SMEM = (E*300 + H*300 + 600 + H + E + 300 + 300)*4;
    static const int DEC_SMEM = (TLOC*H + TLOC*200 + TLOC*SP + 4228)*4;

    cudaFuncSetAttribute(k_encoder, cudaFuncAttributeMaxDynamicSharedMemorySize, ENC_SMEM);
    cudaFuncSetAttribute(k_decoder, cudaFuncAttributeMaxDynamicSharedMemorySize, DEC_SMEM);
    cudaFuncSetAttribute(k_gemm,    cudaFuncAttributeMaxDynamicSharedMemorySize, GSMEM);

    k_encoder<<<B,320,ENC_SMEM>>>(enc_in,femb,encW,encU,encb);
    k_pre    <<<(B*TF)/8,256>>>(attW1,sp1W);
    k_wp     <<<30,256>>>(attW1,attW2,decW,decU,sp1W,sp2W,sp2b);
    k_decoder<<<2*B,1024,DEC_SMEM>>>(decb,sp1b);
    k_wt     <<<NPAD/128,256>>>(ff2W);
    k_ff1    <<<M2,128>>>(ff1W,ff1b);
    k_gemm   <<<dim3(NPAD/128, M2/64),256,GSMEM>>>(ff2b,out);
    k_norm   <<<M2,256>>>(out);
}